// round 15
// baseline (speedup 1.0000x reference)
#include <cuda_runtime.h>
#include <cuda_bf16.h>
#include <cstdint>

// ---------------- problem constants ----------------
#define N_ROWS 4096
#define DIM    2048
#define VOCAB  32000

// ---------------- GEMM tiling ----------------
// 128-thread CTAs, 2 resident per SM: two independent barrier domains per SM
// so one CTA's wait_group/bar.sync no longer stalls the whole SM.
constexpr int BM = 128;
constexpr int BN = 128;
constexpr int BK = 64;                 // 128 bytes bf16 = one SW128 row
constexpr int NSTAGE = 3;
constexpr int KCHUNKS = DIM / BK;      // 32
constexpr uint32_t A_BYTES = BM * BK * 2;            // 16384
constexpr uint32_t B_BYTES = BN * BK * 2;            // 16384
constexpr uint32_t STAGE_BYTES = A_BYTES + B_BYTES;  // 32768
constexpr uint32_t SMEM_TOTAL = NSTAGE * STAGE_BYTES; // 98304 per CTA (x2 = 192K/SM)

// ---------------- device scratch (alloc-free rule: __device__ globals) ----------------
__device__ __nv_bfloat16 g_Abf[(size_t)N_ROWS * DIM];   // input, bf16
__device__ __nv_bfloat16 g_Wt[(size_t)VOCAB * DIM];     // weight^T, bf16, K-contiguous per vocab row
__device__ float g_rowE[N_ROWS];   // sum exp(l - 30)
__device__ float g_rowL[N_ROWS];   // sum l
__device__ float g_rowT[N_ROWS];   // l at target column
__device__ int   g_tgt[N_ROWS];    // normalized int32 targets

// ---------------- helpers ----------------
__device__ __forceinline__ uint32_t smem_u32(const void* p) {
    uint32_t a;
    asm("{ .reg .u64 t; cvta.to.shared.u64 t, %1; cvt.u32.u64 %0, t; }" : "=r"(a) : "l"(p));
    return a;
}
#define SWZ(x) ((x) ^ (((x) >> 3) & 0x70))

__device__ __forceinline__ void ldsm_x4(uint32_t* r, uint32_t addr) {
    asm volatile("ldmatrix.sync.aligned.m8n8.x4.shared.b16 {%0,%1,%2,%3}, [%4];"
                 : "=r"(r[0]), "=r"(r[1]), "=r"(r[2]), "=r"(r[3]) : "r"(addr));
}
__device__ __forceinline__ void mma_16816(float* c, const uint32_t* a, const uint32_t* b) {
    asm volatile(
        "mma.sync.aligned.m16n8k16.row.col.f32.bf16.bf16.f32 "
        "{%0,%1,%2,%3}, {%4,%5,%6,%7}, {%8,%9}, {%0,%1,%2,%3};"
        : "+f"(c[0]), "+f"(c[1]), "+f"(c[2]), "+f"(c[3])
        : "r"(a[0]), "r"(a[1]), "r"(a[2]), "r"(a[3]), "r"(b[0]), "r"(b[1]));
}

// ---------------- pre-pass kernels ----------------
// Zero row accumulators + normalize targets. Reference declares int64 but
// jax-x64-off commonly yields int32; detect layout by scanning would-be high
// words (indices stay inside a 4096-int32 buffer either way, never OOB).
__global__ void k_prep(const int* __restrict__ raw) {
    __shared__ int s_odd;
    if (threadIdx.x == 0) s_odd = 0;
    __syncthreads();
    int local = 0;
    for (int i = threadIdx.x; i < N_ROWS / 2; i += blockDim.x)
        if (raw[2 * i + 1] != 0) local++;
    atomicAdd(&s_odd, local);
    __syncthreads();
    bool is64 = (s_odd < N_ROWS / 4);   // int64 -> high words ~all zero
    for (int i = threadIdx.x; i < N_ROWS; i += blockDim.x) {
        g_tgt[i]  = is64 ? raw[2 * i] : raw[i];
        g_rowE[i] = 0.f; g_rowL[i] = 0.f; g_rowT[i] = 0.f;
    }
}

__global__ void k_convert_input(const float* __restrict__ in) {
    const float4* src = (const float4*)in;
    size_t n4 = (size_t)N_ROWS * DIM / 4;
    for (size_t i = (size_t)blockIdx.x * blockDim.x + threadIdx.x; i < n4;
         i += (size_t)gridDim.x * blockDim.x) {
        float4 v = src[i];
        ((__nv_bfloat162*)g_Abf)[2 * i]     = __floats2bfloat162_rn(v.x, v.y);
        ((__nv_bfloat162*)g_Abf)[2 * i + 1] = __floats2bfloat162_rn(v.z, v.w);
    }
}

// 64x64 tile transpose: float4 coalesced reads, bf16x2 128B-coalesced writes.
__global__ __launch_bounds__(256) void k_transpose_w(const float* __restrict__ w) {
    __shared__ float tile[64][65];
    int v0 = blockIdx.x * 64;
    int k0 = blockIdx.y * 64;
    int tid = threadIdx.x;
    int c4 = tid & 15;          // float4 column within tile
    int r  = tid >> 4;          // 0..15
#pragma unroll
    for (int p = 0; p < 4; ++p) {
        int row = p * 16 + r;   // k index within tile
        const float4 v = *(const float4*)(w + (size_t)(k0 + row) * VOCAB + v0 + c4 * 4);
        tile[row][c4 * 4 + 0] = v.x;
        tile[row][c4 * 4 + 1] = v.y;
        tile[row][c4 * 4 + 2] = v.z;
        tile[row][c4 * 4 + 3] = v.w;
    }
    __syncthreads();
    int lane = tid & 31, warp = tid >> 5;
#pragma unroll
    for (int p = 0; p < 8; ++p) {
        int vv = warp * 8 + p;  // vocab row within tile
        __nv_bfloat162 b = __floats2bfloat162_rn(tile[2 * lane][vv], tile[2 * lane + 1][vv]);
        *((__nv_bfloat162*)(g_Wt + (size_t)(v0 + vv) * DIM + k0) + lane) = b;
    }
}

// ---------------- smem fill: quarter of one BK chunk (A and B) ----------------
// part 0..3; each part issues 2 A + 2 B cp.async per thread (16 total per
// thread per chunk, same as before, but spread across the 4 k-steps so the
// LDGSTS issue burst hides under the MMA stream).
__device__ __forceinline__ void load_part(uint32_t sbase, int s, int k0,
                                          int rowBase, int colBase, int tid, int part) {
    uint32_t aoff = sbase + (uint32_t)s * STAGE_BYTES;
    uint32_t boff = aoff + A_BYTES;
    const char* aSrc = (const char*)(g_Abf + (size_t)rowBase * DIM + k0);
    const char* bSrc = (const char*)(g_Wt  + (size_t)colBase * DIM + k0);
#pragma unroll
    for (int q = 0; q < 2; ++q) {
        int idx = tid + (part * 2 + q) * 128;   // 0..1023 over the 4 parts
        int row = idx >> 3;
        int seg = idx & 7;
        uint32_t sw = SWZ((uint32_t)(row * 128 + seg * 16));
        const void* sa = aSrc + (size_t)row * (DIM * 2) + seg * 16;
        const void* sb = bSrc + (size_t)row * (DIM * 2) + seg * 16;
        asm volatile("cp.async.cg.shared.global [%0], [%1], 16;" :: "r"(aoff + sw), "l"(sa));
        asm volatile("cp.async.cg.shared.global [%0], [%1], 16;" :: "r"(boff + sw), "l"(sb));
    }
}
__device__ __forceinline__ void load_chunk(uint32_t sbase, int s, int k0,
                                           int rowBase, int colBase, int tid) {
#pragma unroll
    for (int part = 0; part < 4; ++part)
        load_part(sbase, s, k0, rowBase, colBase, tid, part);
}

// Load all fragments for one k16 step into buffers af[4][4], bf[4][4]
__device__ __forceinline__ void load_frags(uint32_t as, uint32_t bs, uint32_t kb,
                                           const uint32_t* aPack, const uint32_t* bPack,
                                           uint32_t aK, uint32_t bK,
                                           uint32_t (*af)[4], uint32_t (*bf)[4]) {
#pragma unroll
    for (int mt = 0; mt < 4; ++mt) {
        uint32_t row = aPack[mt] & 0xFFFFu;
        uint32_t msk = aPack[mt] >> 16;
        ldsm_x4(af[mt], as + row + ((kb + aK) ^ msk));
    }
#pragma unroll
    for (int p = 0; p < 4; ++p) {
        uint32_t row = bPack[p] & 0xFFFFu;
        uint32_t msk = bPack[p] >> 16;
        ldsm_x4(bf[p], bs + row + ((kb + bK) ^ msk));
    }
}

// ---------------- fused GEMM + softcap + CE partial reductions ----------------
__global__ __launch_bounds__(128, 2) void k_gemm_ce() {
    extern __shared__ char smem_raw[];
    uint32_t sbase = smem_u32(smem_raw);
    int tid  = threadIdx.x;
    int wid  = tid >> 5;
    int lane = tid & 31;
    int rowBase = blockIdx.x * BM;
    int colBase = blockIdx.y * BN;
    int wm = wid >> 1;     // 0..1  (M warp)  -> 64 rows
    int wn = wid & 1;      // 0..1  (N warp)  -> 64 cols

    // prologue: 2 chunks in flight
    load_chunk(sbase, 0, 0, rowBase, colBase, tid);
    asm volatile("cp.async.commit_group;" ::: "memory");
    load_chunk(sbase, 1, BK, rowBase, colBase, tid);
    asm volatile("cp.async.commit_group;" ::: "memory");

    float acc[4][8][4];
#pragma unroll
    for (int mt = 0; mt < 4; ++mt)
#pragma unroll
        for (int nt = 0; nt < 8; ++nt)
#pragma unroll
            for (int k = 0; k < 4; ++k) acc[mt][nt][k] = 0.f;

    // per-lane ldmatrix addresses, packed (row | mask<<16)
    uint32_t aPack[4], bPack[4];
#pragma unroll
    for (int mt = 0; mt < 4; ++mt) {
        int r = wm * 64 + mt * 16 + (lane & 15);
        aPack[mt] = (uint32_t)(r * 128) | ((uint32_t)((r & 7) << 4) << 16);
    }
#pragma unroll
    for (int p = 0; p < 4; ++p) {
        // x4 B load: lanes 0-15 -> n-tile 2p (k halves), lanes 16-31 -> n-tile 2p+1
        int n = wn * 64 + p * 16 + ((lane >> 4) << 3) + (lane & 7);
        bPack[p] = (uint32_t)(n * 128) | ((uint32_t)((n & 7) << 4) << 16);
    }
    uint32_t aK = (uint32_t)((lane >> 4) * 16);        // which 8-col k-half (A)
    uint32_t bK = (uint32_t)(((lane >> 3) & 1) * 16);  // which 8-col k-half (B)

    uint32_t af[2][4][4], bf[2][4][4];

#pragma unroll 1
    for (int i = 0; i < KCHUNKS; ++i) {
        // chunk i landed (at most 1 group still outstanding)
        asm volatile("cp.async.wait_group 1;" ::: "memory");
        __syncthreads();   // publish chunk i; all warps done reading stage (i+2)%3

        bool doLoad = (i + 2 < KCHUNKS);
        int  ls  = (i + 2) % NSTAGE;
        int  lk0 = (i + 2) * BK;

        uint32_t as = sbase + (uint32_t)(i % NSTAGE) * STAGE_BYTES;
        uint32_t bs = as + A_BYTES;

        // software pipeline across the 4 k16-steps: prefetch ks+1 before MMA(ks);
        // cp.async for chunk i+2 issued a quarter at a time per k-step.
        load_frags(as, bs, 0, aPack, bPack, aK, bK, af[0], bf[0]);
#pragma unroll
        for (int ks = 0; ks < 4; ++ks) {
            int cur = ks & 1;
            if (doLoad)
                load_part(sbase, ls, lk0, rowBase, colBase, tid, ks);
            if (ks < 3)
                load_frags(as, bs, (uint32_t)((ks + 1) * 32), aPack, bPack, aK, bK,
                           af[cur ^ 1], bf[cur ^ 1]);
#pragma unroll
            for (int mt = 0; mt < 4; ++mt)
#pragma unroll
                for (int nt = 0; nt < 8; ++nt)
                    mma_16816(acc[mt][nt], af[cur][mt], &bf[cur][nt >> 1][(nt & 1) * 2]);
        }
        asm volatile("cp.async.commit_group;" ::: "memory");  // uniform group count
    }

    // ---- epilogue: softcap + CE partials straight from accumulators ----
    int quad  = lane >> 2;   // row within 8-row group
    int qlane = lane & 3;    // col pair selector
#pragma unroll
    for (int mt = 0; mt < 4; ++mt) {
#pragma unroll
        for (int half = 0; half < 2; ++half) {
            int row  = rowBase + wm * 64 + mt * 16 + half * 8 + quad;
            int tgtc = g_tgt[row];
            float sE = 0.f, sL = 0.f, sT = 0.f;
#pragma unroll
            for (int nt = 0; nt < 8; ++nt) {
#pragma unroll
                for (int j = 0; j < 2; ++j) {
                    float x = acc[mt][nt][half * 2 + j];
                    float t;
                    asm("tanh.approx.f32 %0, %1;" : "=f"(t) : "f"(x * (1.0f / 30.0f)));
                    float l = 30.0f * t;
                    sL += l;
                    float e;
                    asm("ex2.approx.f32 %0, %1;" : "=f"(e)
                        : "f"((l - 30.0f) * 1.4426950408889634f));
                    sE += e;
                    int col = colBase + wn * 64 + nt * 8 + qlane * 2 + j;
                    if (col == tgtc) sT = l;
                }
            }
            // reduce across the 4 lanes sharing this row
            sE += __shfl_xor_sync(0xffffffffu, sE, 1);
            sE += __shfl_xor_sync(0xffffffffu, sE, 2);
            sL += __shfl_xor_sync(0xffffffffu, sL, 1);
            sL += __shfl_xor_sync(0xffffffffu, sL, 2);
            sT += __shfl_xor_sync(0xffffffffu, sT, 1);
            sT += __shfl_xor_sync(0xffffffffu, sT, 2);
            if (qlane == 0) {
                atomicAdd(&g_rowE[row], sE);
                atomicAdd(&g_rowL[row], sL);
                atomicAdd(&g_rowT[row], sT);
            }
        }
    }
}

// ---------------- finalize: per-row loss terms -> scalar ----------------
__global__ void k_finalize(float* __restrict__ out) {
    __shared__ double s_sum[256];
    __shared__ int    s_cnt[256];
    double acc = 0.0;
    int    cnt = 0;
    for (int r = threadIdx.x; r < N_ROWS; r += 256) {
        int t = g_tgt[r];
        if (t != -100) {
            float lse    = 30.0f + logf(g_rowE[r]);
            float nll    = lse - g_rowT[r];
            float smooth = lse - g_rowL[r] * (1.0f / VOCAB);
            float ce     = 0.9f * nll + 0.1f * smooth;
            float z      = 1e-4f * lse * lse;
            acc += (double)(ce + z);
            cnt++;
        }
    }
    s_sum[threadIdx.x] = acc;
    s_cnt[threadIdx.x] = cnt;
    __syncthreads();
    for (int st = 128; st > 0; st >>= 1) {
        if (threadIdx.x < st) {
            s_sum[threadIdx.x] += s_sum[threadIdx.x + st];
            s_cnt[threadIdx.x] += s_cnt[threadIdx.x + st];
        }
        __syncthreads();
    }
    if (threadIdx.x == 0) out[0] = (float)(s_sum[0] / (double)s_cnt[0]);
}

// ---------------- entry ----------------
extern "C" void kernel_launch(void* const* d_in, const int* in_sizes, int n_in,
                              void* d_out, int out_size) {
    (void)in_sizes; (void)n_in; (void)out_size;
    const float* input  = (const float*)d_in[0];
    const float* weight = (const float*)d_in[1];
    const int*   t_raw  = (const int*)d_in[2];
    float* out = (float*)d_out;

    cudaFuncSetAttribute(k_gemm_ce, cudaFuncAttributeMaxDynamicSharedMemorySize, SMEM_TOTAL);

    k_prep<<<1, 256>>>(t_raw);
    k_convert_input<<<2048, 256>>>(input);
    k_transpose_w<<<dim3(VOCAB / 64, DIM / 64), 256>>>(weight);
    k_gemm_ce<<<dim3(N_ROWS / BM, VOCAB / BN), 128, SMEM_TOTAL>>>();
    k_finalize<<<1, 256>>>(out);
}

// round 16
// speedup vs baseline: 1.0212x; 1.0212x over previous
#include <cuda_runtime.h>
#include <cuda_bf16.h>
#include <cstdint>

// ---------------- problem constants ----------------
#define N_ROWS 4096
#define DIM    2048
#define VOCAB  32000

// ---------------- GEMM tiling ----------------
// 128-thread CTAs, 2 resident per SM: two independent barrier domains per SM
// so one CTA's wait_group/bar.sync no longer stalls the whole SM.
constexpr int BM = 128;
constexpr int BN = 128;
constexpr int BK = 64;                 // 128 bytes bf16 = one SW128 row
constexpr int NSTAGE = 3;
constexpr int KCHUNKS = DIM / BK;      // 32
constexpr uint32_t A_BYTES = BM * BK * 2;            // 16384
constexpr uint32_t B_BYTES = BN * BK * 2;            // 16384
constexpr uint32_t STAGE_BYTES = A_BYTES + B_BYTES;  // 32768
constexpr uint32_t SMEM_TOTAL = NSTAGE * STAGE_BYTES; // 98304 per CTA (x2 = 192K/SM)

// ---------------- device scratch (alloc-free rule: __device__ globals) ----------------
__device__ __nv_bfloat16 g_Abf[(size_t)N_ROWS * DIM];   // input, bf16
__device__ __nv_bfloat16 g_Wt[(size_t)VOCAB * DIM];     // weight^T, bf16, K-contiguous per vocab row
__device__ float g_rowE[N_ROWS];   // sum exp(l - 30)
__device__ float g_rowL[N_ROWS];   // sum l
__device__ float g_rowT[N_ROWS];   // l at target column
__device__ int   g_tgt[N_ROWS];    // normalized int32 targets

// ---------------- helpers ----------------
__device__ __forceinline__ uint32_t smem_u32(const void* p) {
    uint32_t a;
    asm("{ .reg .u64 t; cvta.to.shared.u64 t, %1; cvt.u32.u64 %0, t; }" : "=r"(a) : "l"(p));
    return a;
}
#define SWZ(x) ((x) ^ (((x) >> 3) & 0x70))

__device__ __forceinline__ void ldsm_x4(uint32_t* r, uint32_t addr) {
    asm volatile("ldmatrix.sync.aligned.m8n8.x4.shared.b16 {%0,%1,%2,%3}, [%4];"
                 : "=r"(r[0]), "=r"(r[1]), "=r"(r[2]), "=r"(r[3]) : "r"(addr));
}
__device__ __forceinline__ void mma_16816(float* c, const uint32_t* a, const uint32_t* b) {
    asm volatile(
        "mma.sync.aligned.m16n8k16.row.col.f32.bf16.bf16.f32 "
        "{%0,%1,%2,%3}, {%4,%5,%6,%7}, {%8,%9}, {%0,%1,%2,%3};"
        : "+f"(c[0]), "+f"(c[1]), "+f"(c[2]), "+f"(c[3])
        : "r"(a[0]), "r"(a[1]), "r"(a[2]), "r"(a[3]), "r"(b[0]), "r"(b[1]));
}

// ---------------- pre-pass kernels ----------------
// Zero row accumulators + normalize targets. Reference declares int64 but
// jax-x64-off commonly yields int32; detect layout by scanning would-be high
// words (indices stay inside a 4096-int32 buffer either way, never OOB).
__global__ void k_prep(const int* __restrict__ raw) {
    __shared__ int s_odd;
    if (threadIdx.x == 0) s_odd = 0;
    __syncthreads();
    int local = 0;
    for (int i = threadIdx.x; i < N_ROWS / 2; i += blockDim.x)
        if (raw[2 * i + 1] != 0) local++;
    atomicAdd(&s_odd, local);
    __syncthreads();
    bool is64 = (s_odd < N_ROWS / 4);   // int64 -> high words ~all zero
    for (int i = threadIdx.x; i < N_ROWS; i += blockDim.x) {
        g_tgt[i]  = is64 ? raw[2 * i] : raw[i];
        g_rowE[i] = 0.f; g_rowL[i] = 0.f; g_rowT[i] = 0.f;
    }
}

__global__ void k_convert_input(const float* __restrict__ in) {
    const float4* src = (const float4*)in;
    size_t n4 = (size_t)N_ROWS * DIM / 4;
    for (size_t i = (size_t)blockIdx.x * blockDim.x + threadIdx.x; i < n4;
         i += (size_t)gridDim.x * blockDim.x) {
        float4 v = src[i];
        ((__nv_bfloat162*)g_Abf)[2 * i]     = __floats2bfloat162_rn(v.x, v.y);
        ((__nv_bfloat162*)g_Abf)[2 * i + 1] = __floats2bfloat162_rn(v.z, v.w);
    }
}

// 64x64 tile transpose: float4 coalesced reads, bf16x2 128B-coalesced writes.
__global__ __launch_bounds__(256) void k_transpose_w(const float* __restrict__ w) {
    __shared__ float tile[64][65];
    int v0 = blockIdx.x * 64;
    int k0 = blockIdx.y * 64;
    int tid = threadIdx.x;
    int c4 = tid & 15;          // float4 column within tile
    int r  = tid >> 4;          // 0..15
#pragma unroll
    for (int p = 0; p < 4; ++p) {
        int row = p * 16 + r;   // k index within tile
        const float4 v = *(const float4*)(w + (size_t)(k0 + row) * VOCAB + v0 + c4 * 4);
        tile[row][c4 * 4 + 0] = v.x;
        tile[row][c4 * 4 + 1] = v.y;
        tile[row][c4 * 4 + 2] = v.z;
        tile[row][c4 * 4 + 3] = v.w;
    }
    __syncthreads();
    int lane = tid & 31, warp = tid >> 5;
#pragma unroll
    for (int p = 0; p < 8; ++p) {
        int vv = warp * 8 + p;  // vocab row within tile
        __nv_bfloat162 b = __floats2bfloat162_rn(tile[2 * lane][vv], tile[2 * lane + 1][vv]);
        *((__nv_bfloat162*)(g_Wt + (size_t)(v0 + vv) * DIM + k0) + lane) = b;
    }
}

// ---------------- smem fill: one BK chunk of A and B (128 threads) ----------------
__device__ __forceinline__ void load_chunk(uint32_t sbase, int s, int k0,
                                           int rowBase, int colBase, int tid) {
    uint32_t aoff = sbase + (uint32_t)s * STAGE_BYTES;
    uint32_t boff = aoff + A_BYTES;
    const char* aSrc = (const char*)(g_Abf + (size_t)rowBase * DIM + k0);
    const char* bSrc = (const char*)(g_Wt  + (size_t)colBase * DIM + k0);
    // A and B: 128 rows x 8 x 16B segs each = 1024 segs -> 8 per thread
#pragma unroll
    for (int q = 0; q < 8; ++q) {
        int idx = tid + q * 128;
        int row = idx >> 3;
        int seg = idx & 7;
        uint32_t sw = SWZ((uint32_t)(row * 128 + seg * 16));
        const void* sa = aSrc + (size_t)row * (DIM * 2) + seg * 16;
        const void* sb = bSrc + (size_t)row * (DIM * 2) + seg * 16;
        asm volatile("cp.async.cg.shared.global [%0], [%1], 16;" :: "r"(aoff + sw), "l"(sa));
        asm volatile("cp.async.cg.shared.global [%0], [%1], 16;" :: "r"(boff + sw), "l"(sb));
    }
}

// Load all fragments for one k16 step into buffers af[4][4], bf[4][4]
__device__ __forceinline__ void load_frags(uint32_t as, uint32_t bs, uint32_t kb,
                                           const uint32_t* aPack, const uint32_t* bPack,
                                           uint32_t aK, uint32_t bK,
                                           uint32_t (*af)[4], uint32_t (*bf)[4]) {
#pragma unroll
    for (int mt = 0; mt < 4; ++mt) {
        uint32_t row = aPack[mt] & 0xFFFFu;
        uint32_t msk = aPack[mt] >> 16;
        ldsm_x4(af[mt], as + row + ((kb + aK) ^ msk));
    }
#pragma unroll
    for (int p = 0; p < 4; ++p) {
        uint32_t row = bPack[p] & 0xFFFFu;
        uint32_t msk = bPack[p] >> 16;
        ldsm_x4(bf[p], bs + row + ((kb + bK) ^ msk));
    }
}

// ---------------- fused GEMM + softcap + CE partial reductions ----------------
__global__ __launch_bounds__(128, 2) void k_gemm_ce() {
    extern __shared__ char smem_raw[];
    uint32_t sbase = smem_u32(smem_raw);
    int tid  = threadIdx.x;
    int wid  = tid >> 5;
    int lane = tid & 31;
    int rowBase = blockIdx.x * BM;
    int colBase = blockIdx.y * BN;
    int wm = wid >> 1;     // 0..1  (M warp)  -> 64 rows
    int wn = wid & 1;      // 0..1  (N warp)  -> 64 cols

    // prologue: 2 chunks in flight
    load_chunk(sbase, 0, 0, rowBase, colBase, tid);
    asm volatile("cp.async.commit_group;" ::: "memory");
    load_chunk(sbase, 1, BK, rowBase, colBase, tid);
    asm volatile("cp.async.commit_group;" ::: "memory");

    float acc[4][8][4];
#pragma unroll
    for (int mt = 0; mt < 4; ++mt)
#pragma unroll
        for (int nt = 0; nt < 8; ++nt)
#pragma unroll
            for (int k = 0; k < 4; ++k) acc[mt][nt][k] = 0.f;

    // per-lane ldmatrix addresses, packed (row | mask<<16)
    uint32_t aPack[4], bPack[4];
#pragma unroll
    for (int mt = 0; mt < 4; ++mt) {
        int r = wm * 64 + mt * 16 + (lane & 15);
        aPack[mt] = (uint32_t)(r * 128) | ((uint32_t)((r & 7) << 4) << 16);
    }
#pragma unroll
    for (int p = 0; p < 4; ++p) {
        // x4 B load: lanes 0-15 -> n-tile 2p (k halves), lanes 16-31 -> n-tile 2p+1
        int n = wn * 64 + p * 16 + ((lane >> 4) << 3) + (lane & 7);
        bPack[p] = (uint32_t)(n * 128) | ((uint32_t)((n & 7) << 4) << 16);
    }
    uint32_t aK = (uint32_t)((lane >> 4) * 16);        // which 8-col k-half (A)
    uint32_t bK = (uint32_t)(((lane >> 3) & 1) * 16);  // which 8-col k-half (B)

    uint32_t af[2][4][4], bf[2][4][4];

#pragma unroll 1
    for (int i = 0; i < KCHUNKS; ++i) {
        // chunk i landed (at most 1 group still outstanding)
        asm volatile("cp.async.wait_group 1;" ::: "memory");
        __syncthreads();   // publish chunk i; all warps done reading stage (i+2)%3

        // issue next load BEFORE compute so it overlaps the MMAs
        if (i + 2 < KCHUNKS)
            load_chunk(sbase, (i + 2) % NSTAGE, (i + 2) * BK, rowBase, colBase, tid);
        asm volatile("cp.async.commit_group;" ::: "memory");  // uniform group count

        uint32_t as = sbase + (uint32_t)(i % NSTAGE) * STAGE_BYTES;
        uint32_t bs = as + A_BYTES;

        // software pipeline across the 4 k16-steps: prefetch ks+1 before MMA(ks)
        load_frags(as, bs, 0, aPack, bPack, aK, bK, af[0], bf[0]);
#pragma unroll
        for (int ks = 0; ks < 4; ++ks) {
            int cur = ks & 1;
            if (ks < 3)
                load_frags(as, bs, (uint32_t)((ks + 1) * 32), aPack, bPack, aK, bK,
                           af[cur ^ 1], bf[cur ^ 1]);
#pragma unroll
            for (int mt = 0; mt < 4; ++mt)
#pragma unroll
                for (int nt = 0; nt < 8; ++nt)
                    mma_16816(acc[mt][nt], af[cur][mt], &bf[cur][nt >> 1][(nt & 1) * 2]);
        }
    }

    // ---- epilogue: softcap + CE partials straight from accumulators ----
    int quad  = lane >> 2;   // row within 8-row group
    int qlane = lane & 3;    // col pair selector
#pragma unroll
    for (int mt = 0; mt < 4; ++mt) {
#pragma unroll
        for (int half = 0; half < 2; ++half) {
            int row  = rowBase + wm * 64 + mt * 16 + half * 8 + quad;
            int tgtc = g_tgt[row];
            float sE = 0.f, sL = 0.f, sT = 0.f;
#pragma unroll
            for (int nt = 0; nt < 8; ++nt) {
#pragma unroll
                for (int j = 0; j < 2; ++j) {
                    float x = acc[mt][nt][half * 2 + j];
                    float t;
                    asm("tanh.approx.f32 %0, %1;" : "=f"(t) : "f"(x * (1.0f / 30.0f)));
                    float l = 30.0f * t;
                    sL += l;
                    float e;
                    asm("ex2.approx.f32 %0, %1;" : "=f"(e)
                        : "f"((l - 30.0f) * 1.4426950408889634f));
                    sE += e;
                    int col = colBase + wn * 64 + nt * 8 + qlane * 2 + j;
                    if (col == tgtc) sT = l;
                }
            }
            // reduce across the 4 lanes sharing this row
            sE += __shfl_xor_sync(0xffffffffu, sE, 1);
            sE += __shfl_xor_sync(0xffffffffu, sE, 2);
            sL += __shfl_xor_sync(0xffffffffu, sL, 1);
            sL += __shfl_xor_sync(0xffffffffu, sL, 2);
            sT += __shfl_xor_sync(0xffffffffu, sT, 1);
            sT += __shfl_xor_sync(0xffffffffu, sT, 2);
            if (qlane == 0) {
                atomicAdd(&g_rowE[row], sE);
                atomicAdd(&g_rowL[row], sL);
                atomicAdd(&g_rowT[row], sT);
            }
        }
    }
}

// ---------------- finalize: per-row loss terms -> scalar ----------------
__global__ void k_finalize(float* __restrict__ out) {
    __shared__ double s_sum[256];
    __shared__ int    s_cnt[256];
    double acc = 0.0;
    int    cnt = 0;
    for (int r = threadIdx.x; r < N_ROWS; r += 256) {
        int t = g_tgt[r];
        if (t != -100) {
            float lse    = 30.0f + logf(g_rowE[r]);
            float nll    = lse - g_rowT[r];
            float smooth = lse - g_rowL[r] * (1.0f / VOCAB);
            float ce     = 0.9f * nll + 0.1f * smooth;
            float z      = 1e-4f * lse * lse;
            acc += (double)(ce + z);
            cnt++;
        }
    }
    s_sum[threadIdx.x] = acc;
    s_cnt[threadIdx.x] = cnt;
    __syncthreads();
    for (int st = 128; st > 0; st >>= 1) {
        if (threadIdx.x < st) {
            s_sum[threadIdx.x] += s_sum[threadIdx.x + st];
            s_cnt[threadIdx.x] += s_cnt[threadIdx.x + st];
        }
        __syncthreads();
    }
    if (threadIdx.x == 0) out[0] = (float)(s_sum[0] / (double)s_cnt[0]);
}

// ---------------- entry ----------------
extern "C" void kernel_launch(void* const* d_in, const int* in_sizes, int n_in,
                              void* d_out, int out_size) {
    (void)in_sizes; (void)n_in; (void)out_size;
    const float* input  = (const float*)d_in[0];
    const float* weight = (const float*)d_in[1];
    const int*   t_raw  = (const int*)d_in[2];
    float* out = (float*)d_out;

    cudaFuncSetAttribute(k_gemm_ce, cudaFuncAttributeMaxDynamicSharedMemorySize, SMEM_TOTAL);

    k_prep<<<1, 256>>>(t_raw);
    k_convert_input<<<2048, 256>>>(input);
    k_transpose_w<<<dim3(VOCAB / 64, DIM / 64), 256>>>(weight);
    k_gemm_ce<<<dim3(N_ROWS / BM, VOCAB / BN), 128, SMEM_TOTAL>>>();
    k_finalize<<<1, 256>>>(out);
}